// round 2
// baseline (speedup 1.0000x reference)
#include <cuda_runtime.h>
#include <cstdint>
#include <cstddef>

#define Dv 100

typedef unsigned long long ull;

__device__ __forceinline__ void ffma2(ull &d, ull a, ull b) {
    asm("fma.rn.f32x2 %0, %1, %2, %0;" : "+l"(d) : "l"(a), "l"(b));
}
__device__ __forceinline__ ull pack2(float lo, float hi) {
    ull r; asm("mov.b64 %0, {%1, %2};" : "=l"(r) : "f"(lo), "f"(hi)); return r;
}
__device__ __forceinline__ float2 unpack2(ull v) {
    float2 r; asm("mov.b64 {%0, %1}, %2;" : "=f"(r.x), "=f"(r.y) : "l"(v)); return r;
}

struct Smem {
    float4 w0s[4][Dv][9];     // [i4][j][tt(+pad)] : W0[t0+tt][4*i4+c][j]
    float  xs[Dv][68];        // [j][bb(+pad)]
    float  las[Dv][8];        // log_alpha[j][t0+tt], -3e38 if j==t or t>=100
    float  w1s[16][8][8][2];  // [jj][i2][tt][half] : W1[t][2*i2+half][jj]
    float  b0s[8][16];
    float  b1s[8][16];
    float  w2s[8][2][16];
    float  b2s[8][2];
};

__global__ __launch_bounds__(128)
void fused_nri_kernel(const float* __restrict__ x,
                      const float* __restrict__ la_g,
                      const float* __restrict__ noise,
                      const float* __restrict__ W0,
                      const float* __restrict__ b0g,
                      const float* __restrict__ W1,
                      const float* __restrict__ b1g,
                      const float* __restrict__ W2,
                      const float* __restrict__ b2g,
                      float* __restrict__ out)
{
    extern __shared__ char smem_raw[];
    Smem& S = *reinterpret_cast<Smem*>(smem_raw);
    const int tid = threadIdx.x;
    const int t_tile = blockIdx.x >> 6;   // / 64
    const int b_blk  = blockIdx.x & 63;
    const int t0 = t_tile * 8;
    const int bbase = b_blk * 64;

    // ---- stage W0 tile: src coalesced over j, dst [i4][j][tt] float4 ----
    for (int e = tid; e < 8 * 16 * Dv; e += 128) {
        int tt = e / (16 * Dv);
        int r  = e - tt * 16 * Dv;
        int i  = r / Dv;
        int j  = r - i * Dv;
        int t  = t0 + tt;
        float v = (t < Dv) ? W0[(t * 16 + i) * Dv + j] : 0.f;
        reinterpret_cast<float*>(&S.w0s[i >> 2][j][tt])[i & 3] = v;
    }
    // ---- stage x tile transposed ----
    for (int e = tid; e < 64 * Dv; e += 128) {
        int bb = e / Dv;
        int j  = e - bb * Dv;
        S.xs[j][bb] = x[(bbase + bb) * Dv + j];
    }
    // ---- stage log_alpha with adj + tile-guard folded in ----
    for (int e = tid; e < 8 * Dv; e += 128) {
        int j = e >> 3, tt = e & 7, t = t0 + tt;
        float v = -3e38f;
        if (t < Dv && j != t) v = la_g[j * Dv + t];
        S.las[j][tt] = v;
    }
    // ---- W1 as i-pairs for f32x2 ----
    for (int e = tid; e < 8 * 16 * 16; e += 128) {
        int tt = e >> 8, r = e & 255, i = r >> 4, jj = r & 15, t = t0 + tt;
        S.w1s[jj][i >> 1][tt][i & 1] = (t < Dv) ? W1[(t * 16 + i) * 16 + jj] : 0.f;
    }
    // ---- biases, W2 ----
    {
        int e = tid;  // 128 elements exactly
        int tt = e >> 4, i = e & 15, t = t0 + tt;
        S.b0s[tt][i] = (t < Dv) ? b0g[t * 16 + i] : 0.f;
        S.b1s[tt][i] = (t < Dv) ? b1g[t * 16 + i] : 0.f;
    }
    for (int e = tid; e < 8 * 2 * 16; e += 128) {
        int tt = e >> 5, r = e & 31, p = r >> 4, jj = r & 15, t = t0 + tt;
        S.w2s[tt][p][jj] = (t < Dv) ? W2[(t * 2 + p) * 16 + jj] : 0.f;
    }
    if (tid < 16) {
        int tt = tid >> 1, p = tid & 1, t = t0 + tt;
        S.b2s[tt][p] = (t < Dv) ? b2g[t * 2 + p] : 0.f;
    }
    __syncthreads();

    const int lane = tid & 31;
    const int warp = tid >> 5;
    const int tt   = lane & 7;     // 8 consecutive t per warp -> full 32B noise sectors
    const int bbg  = lane >> 3;
    const int t    = t0 + tt;
    const int t_eff = (t < Dv) ? t : (Dv - 1);
    const int bb0  = warp * 16 + bbg * 4;   // this thread's 4 batch rows

    const float* np0 = noise + (size_t)(bbase + bb0) * (Dv * Dv) + t_eff;
    const float* np1 = np0 + Dv * Dv;
    const float* np2 = np1 + Dv * Dv;
    const float* np3 = np2 + Dv * Dv;

    ull acc[4][8];
    #pragma unroll
    for (int k = 0; k < 4; k++)
        #pragma unroll
        for (int i = 0; i < 8; i++) acc[k][i] = 0ull;

    // software-pipelined j loop (prefetch distance 1)
    float n_nx0 = np0[0], n_nx1 = np1[0], n_nx2 = np2[0], n_nx3 = np3[0];
    float la_nx = S.las[0][tt];
    float4 x_nx = *reinterpret_cast<const float4*>(&S.xs[0][bb0]);

    #pragma unroll 4
    for (int j = 0; j < Dv; j++) {
        float nc0 = n_nx0, nc1 = n_nx1, nc2 = n_nx2, nc3 = n_nx3;
        float lac = la_nx;
        float4 xc = x_nx;

        // W0 column for this j: 4x conflict-free LDS.128
        float4 wa = S.w0s[0][j][tt];
        float4 wb = S.w0s[1][j][tt];
        float4 wc = S.w0s[2][j][tt];
        float4 wd = S.w0s[3][j][tt];

        int jn = (j + 1 < Dv) ? j + 1 : Dv - 1;
        n_nx0 = np0[jn * Dv]; n_nx1 = np1[jn * Dv];
        n_nx2 = np2[jn * Dv]; n_nx3 = np3[jn * Dv];
        la_nx = S.las[jn][tt];
        x_nx  = *reinterpret_cast<const float4*>(&S.xs[jn][bb0]);

        ull w01 = pack2(wa.x, wa.y), w23 = pack2(wa.z, wa.w);
        ull w45 = pack2(wb.x, wb.y), w67 = pack2(wb.z, wb.w);
        ull w89 = pack2(wc.x, wc.y), wab = pack2(wc.z, wc.w);
        ull wcd = pack2(wd.x, wd.y), wef = pack2(wd.z, wd.w);

        // hard Gumbel-sigmoid mask folded into x (no divergence)
        float xm0 = (lac + nc0 > 0.f) ? xc.x : 0.f;
        float xm1 = (lac + nc1 > 0.f) ? xc.y : 0.f;
        float xm2 = (lac + nc2 > 0.f) ? xc.z : 0.f;
        float xm3 = (lac + nc3 > 0.f) ? xc.w : 0.f;
        ull xp0 = pack2(xm0, xm0), xp1 = pack2(xm1, xm1);
        ull xp2 = pack2(xm2, xm2), xp3 = pack2(xm3, xm3);

        #define L0ROW(k, xp)                                     \
            ffma2(acc[k][0], w01, xp); ffma2(acc[k][1], w23, xp); \
            ffma2(acc[k][2], w45, xp); ffma2(acc[k][3], w67, xp); \
            ffma2(acc[k][4], w89, xp); ffma2(acc[k][5], wab, xp); \
            ffma2(acc[k][6], wcd, xp); ffma2(acc[k][7], wef, xp);
        L0ROW(0, xp0) L0ROW(1, xp1) L0ROW(2, xp2) L0ROW(3, xp3)
        #undef L0ROW
    }

    // ---- layers 1 & 2 epilogue ----
    if (t < Dv) {
        #pragma unroll
        for (int k = 0; k < 4; k++) {
            float h[16];
            #pragma unroll
            for (int i2 = 0; i2 < 8; i2++) {
                float2 v = unpack2(acc[k][i2]);
                float a0 = v.x + S.b0s[tt][2 * i2];
                float a1 = v.y + S.b0s[tt][2 * i2 + 1];
                h[2 * i2]     = a0 > 0.f ? a0 : 0.01f * a0;   // leaky_relu(0.01)
                h[2 * i2 + 1] = a1 > 0.f ? a1 : 0.01f * a1;
            }
            ull a2[8];
            #pragma unroll
            for (int i2 = 0; i2 < 8; i2++)
                a2[i2] = pack2(S.b1s[tt][2 * i2], S.b1s[tt][2 * i2 + 1]);
            #pragma unroll
            for (int jj = 0; jj < 16; jj++) {
                ull hv = pack2(h[jj], h[jj]);
                #pragma unroll
                for (int i2 = 0; i2 < 8; i2++) {
                    ull wv = *reinterpret_cast<const ull*>(&S.w1s[jj][i2][tt][0]);
                    ffma2(a2[i2], wv, hv);
                }
            }
            float o0 = S.b2s[tt][0], o1 = S.b2s[tt][1];
            #pragma unroll
            for (int i2 = 0; i2 < 8; i2++) {
                float2 v = unpack2(a2[i2]);
                float g0 = v.x > 0.f ? v.x : 0.01f * v.x;
                float g1 = v.y > 0.f ? v.y : 0.01f * v.y;
                o0 += S.w2s[tt][0][2 * i2] * g0 + S.w2s[tt][0][2 * i2 + 1] * g1;
                o1 += S.w2s[tt][1][2 * i2] * g0 + S.w2s[tt][1][2 * i2 + 1] * g1;
            }
            int b = bbase + bb0 + k;
            reinterpret_cast<float2*>(out)[b * Dv + t] = make_float2(o0, o1);
        }
    }
}

extern "C" void kernel_launch(void* const* d_in, const int* in_sizes, int n_in,
                              void* d_out, int out_size)
{
    const float* x   = (const float*)d_in[0];
    const float* la  = (const float*)d_in[1];
    const float* nz  = (const float*)d_in[2];
    const float* W0  = (const float*)d_in[3];
    const float* b0  = (const float*)d_in[4];
    const float* W1  = (const float*)d_in[5];
    const float* b1  = (const float*)d_in[6];
    const float* W2  = (const float*)d_in[7];
    const float* b2  = (const float*)d_in[8];
    float* out = (float*)d_out;

    cudaFuncSetAttribute(fused_nri_kernel,
                         cudaFuncAttributeMaxDynamicSharedMemorySize,
                         (int)sizeof(Smem));
    // 13 t-tiles (T_TILE=8 over D=100) x 64 b-blocks (B_TILE=64 over 4096)
    fused_nri_kernel<<<13 * 64, 128, sizeof(Smem)>>>(
        x, la, nz, W0, b0, W1, b1, W2, b2, out);
}

// round 3
// speedup vs baseline: 1.1341x; 1.1341x over previous
#include <cuda_runtime.h>
#include <cstdint>
#include <cstddef>

#define Dv 100
typedef unsigned long long ull;

__device__ __forceinline__ void ffma2(ull &d, ull a, ull b) {
    asm("fma.rn.f32x2 %0, %1, %2, %0;" : "+l"(d) : "l"(a), "l"(b));
}
__device__ __forceinline__ ull dup2(float v) {
    ull r; asm("mov.b64 %0, {%1, %1};" : "=l"(r) : "f"(v)); return r;
}
__device__ __forceinline__ ull pack2(float lo, float hi) {
    ull r; asm("mov.b64 %0, {%1, %2};" : "=l"(r) : "f"(lo), "f"(hi)); return r;
}
__device__ __forceinline__ float2 unpack2(ull v) {
    float2 r; asm("mov.b64 {%0, %1}, %2;" : "=f"(r.x), "=f"(r.y) : "l"(v)); return r;
}
__device__ __forceinline__ void lds_v2u64(ull &a, ull &b, const void* p) {
    unsigned sa = (unsigned)__cvta_generic_to_shared(p);
    asm("ld.shared.v2.u64 {%0, %1}, [%2];" : "=l"(a), "=l"(b) : "r"(sa));
}
// (mz >= 0) ? 0 : x  — with mz = -(la+noise) this is exactly (la+noise > 0) ? x : 0
__device__ __forceinline__ float slct0(float x, float mz) {
    float r;
    asm("slct.f32.f32 %0, %1, %2, %3;" : "=f"(r) : "f"(0.0f), "f"(x), "f"(mz));
    return r;
}

struct Smem {
    float4 w0s[Dv][4][8];     // [j][i4][tt] : (W0[t0+tt][4*i4+c][j])c=0..3   51.2KB
    float  xs[64][108];       // [bb][j(+pad)]                                27.6KB
    float  las[Dv][8];        // log_alpha[j][t0+tt], -3e38 if j==t or t>=100  3.2KB
    float  w1s[16][8][8][2];  // [jj][i2][tt][half] : W1[t][2*i2+half][jj]    16.4KB
    float  b0s[8][16];
    float  b1s[8][16];
    float  w2s[8][2][16];
    float  b2s[8][2];
};

__global__ __launch_bounds__(256, 2)
void fused_nri_kernel(const float* __restrict__ x,
                      const float* __restrict__ la_g,
                      const float* __restrict__ noise,
                      const float* __restrict__ W0,
                      const float* __restrict__ b0g,
                      const float* __restrict__ W1,
                      const float* __restrict__ b1g,
                      const float* __restrict__ W2,
                      const float* __restrict__ b2g,
                      float* __restrict__ out)
{
    extern __shared__ char smem_raw[];
    Smem& S = *reinterpret_cast<Smem*>(smem_raw);
    const int tid = threadIdx.x;
    const int t_tile = blockIdx.x >> 6;
    const int b_blk  = blockIdx.x & 63;
    const int t0 = t_tile * 8;
    const int bbase = b_blk * 64;

    // ---- stage W0 tile (coalesced over j) ----
    for (int e = tid; e < 8 * 16 * Dv; e += 256) {
        int tt = e / (16 * Dv);
        int r  = e - tt * 16 * Dv;
        int i  = r / Dv;
        int j  = r - i * Dv;
        int t  = t0 + tt;
        float v = (t < Dv) ? W0[(t * 16 + i) * Dv + j] : 0.f;
        reinterpret_cast<float*>(&S.w0s[j][i >> 2][tt])[i & 3] = v;
    }
    // ---- stage x tile [bb][j] ----
    for (int e = tid; e < 64 * Dv; e += 256) {
        int bb = e / Dv;
        int j  = e - bb * Dv;
        S.xs[bb][j] = x[(bbase + bb) * Dv + j];
    }
    // ---- log_alpha with adj + tile guard folded in ----
    for (int e = tid; e < 8 * Dv; e += 256) {
        int j = e >> 3, tt = e & 7, t = t0 + tt;
        float v = -3e38f;
        if (t < Dv && j != t) v = la_g[j * Dv + t];
        S.las[j][tt] = v;
    }
    // ---- W1 as i-pairs ----
    for (int e = tid; e < 8 * 16 * 16; e += 256) {
        int tt = e >> 8, r = e & 255, i = r >> 4, jj = r & 15, t = t0 + tt;
        S.w1s[jj][i >> 1][tt][i & 1] = (t < Dv) ? W1[(t * 16 + i) * 16 + jj] : 0.f;
    }
    // ---- biases, W2 ----
    if (tid < 128) {
        int tt = tid >> 4, i = tid & 15, t = t0 + tt;
        S.b0s[tt][i] = (t < Dv) ? b0g[t * 16 + i] : 0.f;
        S.b1s[tt][i] = (t < Dv) ? b1g[t * 16 + i] : 0.f;
    }
    for (int e = tid; e < 8 * 2 * 16; e += 256) {
        int tt = e >> 5, r = e & 31, p = r >> 4, jj = r & 15, t = t0 + tt;
        S.w2s[tt][p][jj] = (t < Dv) ? W2[(t * 2 + p) * 16 + jj] : 0.f;
    }
    if (tid < 16) {
        int tt = tid >> 1, p = tid & 1, t = t0 + tt;
        S.b2s[tt][p] = (t < Dv) ? b2g[t * 2 + p] : 0.f;
    }
    __syncthreads();

    const int lane = tid & 31;
    const int warp = tid >> 5;
    const int tt   = lane & 7;          // 8 consecutive t -> full 32B noise sectors
    const int bbg  = lane >> 3;
    const int t    = t0 + tt;
    const int t_eff = (t < Dv) ? t : (Dv - 1);
    const int bb0  = warp * 8 + bbg * 2;    // 2 batch rows per thread

    const float* np0 = noise + (size_t)(bbase + bb0) * (Dv * Dv) + t_eff;
    const float* np1 = np0 + Dv * Dv;

    ull acc[2][8];
    #pragma unroll
    for (int k = 0; k < 2; k++)
        #pragma unroll
        for (int i = 0; i < 8; i++) acc[k][i] = 0ull;

    // ---- pipelined j loop: groups of 4 j; noise prefetched 2 groups ahead ----
    float nz[2][2][4];        // [phase][b][jj]
    #define LOADG(buf, jb) do { int _o = (jb) * Dv;                              \
        buf[0][0] = np0[_o];          buf[0][1] = np0[_o + Dv];                  \
        buf[0][2] = np0[_o + 2 * Dv]; buf[0][3] = np0[_o + 3 * Dv];              \
        buf[1][0] = np1[_o];          buf[1][1] = np1[_o + Dv];                  \
        buf[1][2] = np1[_o + 2 * Dv]; buf[1][3] = np1[_o + 3 * Dv]; } while (0)

    LOADG(nz[0], 0);
    LOADG(nz[1], 4);
    float4 xn0 = *reinterpret_cast<const float4*>(&S.xs[bb0][0]);
    float4 xn1 = *reinterpret_cast<const float4*>(&S.xs[bb0 + 1][0]);
    float lan[4] = { S.las[0][tt], S.las[1][tt], S.las[2][tt], S.las[3][tt] };

    #pragma unroll 2
    for (int jc = 0; jc < 25; jc++) {
        const int ph = jc & 1;
        const int jb = jc * 4;
        // snapshot current group
        float cn0[4], cn1[4];
        #pragma unroll
        for (int jj = 0; jj < 4; jj++) { cn0[jj] = nz[ph][0][jj]; cn1[jj] = nz[ph][1][jj]; }
        float4 xc0 = xn0, xc1 = xn1;
        float lac[4] = { lan[0], lan[1], lan[2], lan[3] };

        // prefetch noise two groups ahead
        int jpre = (jc + 2 < 25) ? (jc + 2) * 4 : 96;
        LOADG(nz[ph], jpre);
        // prefetch x/la one group ahead
        int jnx = (jc + 1 < 25) ? (jc + 1) * 4 : 96;
        xn0 = *reinterpret_cast<const float4*>(&S.xs[bb0][jnx]);
        xn1 = *reinterpret_cast<const float4*>(&S.xs[bb0 + 1][jnx]);
        #pragma unroll
        for (int jj = 0; jj < 4; jj++) lan[jj] = S.las[jnx + jj][tt];

        const float xc0a[4] = { xc0.x, xc0.y, xc0.z, xc0.w };
        const float xc1a[4] = { xc1.x, xc1.y, xc1.z, xc1.w };

        #pragma unroll
        for (int jj = 0; jj < 4; jj++) {
            const int j = jb + jj;
            ull w[8];
            lds_v2u64(w[0], w[1], &S.w0s[j][0][tt]);
            lds_v2u64(w[2], w[3], &S.w0s[j][1][tt]);
            lds_v2u64(w[4], w[5], &S.w0s[j][2][tt]);
            lds_v2u64(w[6], w[7], &S.w0s[j][3][tt]);

            float mz0 = (-lac[jj]) - cn0[jj];      // -(la + noise)
            float mz1 = (-lac[jj]) - cn1[jj];
            ull xp0 = dup2(slct0(xc0a[jj], mz0));
            ull xp1 = dup2(slct0(xc1a[jj], mz1));

            #pragma unroll
            for (int i = 0; i < 8; i++) ffma2(acc[0][i], w[i], xp0);
            #pragma unroll
            for (int i = 0; i < 8; i++) ffma2(acc[1][i], w[i], xp1);
        }
    }
    #undef LOADG

    // ---- layers 1 & 2 epilogue ----
    if (t < Dv) {
        #pragma unroll
        for (int k = 0; k < 2; k++) {
            float h[16];
            #pragma unroll
            for (int i2 = 0; i2 < 8; i2++) {
                float2 v = unpack2(acc[k][i2]);
                float a0 = v.x + S.b0s[tt][2 * i2];
                float a1 = v.y + S.b0s[tt][2 * i2 + 1];
                h[2 * i2]     = a0 > 0.f ? a0 : 0.01f * a0;
                h[2 * i2 + 1] = a1 > 0.f ? a1 : 0.01f * a1;
            }
            ull a2[8];
            #pragma unroll
            for (int i2 = 0; i2 < 8; i2++)
                a2[i2] = pack2(S.b1s[tt][2 * i2], S.b1s[tt][2 * i2 + 1]);
            #pragma unroll
            for (int jj = 0; jj < 16; jj++) {
                ull hv = dup2(h[jj]);
                #pragma unroll
                for (int i2 = 0; i2 < 8; i2++) {
                    ull wv = *reinterpret_cast<const ull*>(&S.w1s[jj][i2][tt][0]);
                    ffma2(a2[i2], wv, hv);
                }
            }
            float o0 = S.b2s[tt][0], o1 = S.b2s[tt][1];
            #pragma unroll
            for (int i2 = 0; i2 < 8; i2++) {
                float2 v = unpack2(a2[i2]);
                float g0 = v.x > 0.f ? v.x : 0.01f * v.x;
                float g1 = v.y > 0.f ? v.y : 0.01f * v.y;
                o0 += S.w2s[tt][0][2 * i2] * g0 + S.w2s[tt][0][2 * i2 + 1] * g1;
                o1 += S.w2s[tt][1][2 * i2] * g0 + S.w2s[tt][1][2 * i2 + 1] * g1;
            }
            int b = bbase + bb0 + k;
            reinterpret_cast<float2*>(out)[b * Dv + t] = make_float2(o0, o1);
        }
    }
}

extern "C" void kernel_launch(void* const* d_in, const int* in_sizes, int n_in,
                              void* d_out, int out_size)
{
    const float* x   = (const float*)d_in[0];
    const float* la  = (const float*)d_in[1];
    const float* nz  = (const float*)d_in[2];
    const float* W0  = (const float*)d_in[3];
    const float* b0  = (const float*)d_in[4];
    const float* W1  = (const float*)d_in[5];
    const float* b1  = (const float*)d_in[6];
    const float* W2  = (const float*)d_in[7];
    const float* b2  = (const float*)d_in[8];
    float* out = (float*)d_out;

    cudaFuncSetAttribute(fused_nri_kernel,
                         cudaFuncAttributeMaxDynamicSharedMemorySize,
                         (int)sizeof(Smem));
    fused_nri_kernel<<<13 * 64, 256, sizeof(Smem)>>>(
        x, la, nz, W0, b0, W1, b1, W2, b2, out);
}